// round 4
// baseline (speedup 1.0000x reference)
#include <cuda_runtime.h>

#define Nn 200000
#define Ee 3200000
#define IND 165
#define HID 64
#define NB1K 196   // ceil(Nn/1024)

// ---- scratch (no cudaMalloc allowed) ----
__device__ float g_h0[Nn * HID];
__device__ float g_h1[Nn * HID];
__device__ int   g_degi[Nn];
__device__ int   g_off[Nn];
__device__ int   g_cur[Nn];
__device__ int   g_csr[Ee];
__device__ int   g_bsum[256];
__device__ int   g_bscan[256];

// ---- packed f32x2 helpers (sm_103a) ----
typedef unsigned long long u64;
__device__ __forceinline__ u64 pack2(float v) {
    u64 r; asm("mov.b64 %0, {%1, %1};" : "=l"(r) : "f"(v)); return r;
}
__device__ __forceinline__ u64 packxy(float x, float y) {
    u64 r; asm("mov.b64 %0, {%1, %2};" : "=l"(r) : "f"(x), "f"(y)); return r;
}
__device__ __forceinline__ u64 fma2(u64 a, u64 b, u64 c) {
    u64 d; asm("fma.rn.f32x2 %0, %1, %2, %3;" : "=l"(d) : "l"(a), "l"(b), "l"(c)); return d;
}
__device__ __forceinline__ float2 unpack2(u64 v) {
    float2 f; asm("mov.b64 {%0, %1}, %2;" : "=f"(f.x), "=f"(f.y) : "l"(v)); return f;
}

// =================== degree histogram (int4, 4 edges/thread) ===================
__global__ __launch_bounds__(256) void deg_kernel(const int* __restrict__ dst, int* __restrict__ degi)
{
    int t = blockIdx.x * blockDim.x + threadIdx.x;
    if (t < Ee / 4) {
        int4 d4 = reinterpret_cast<const int4*>(dst)[t];
        atomicAdd(&degi[d4.x], 1);
        atomicAdd(&degi[d4.y], 1);
        atomicAdd(&degi[d4.z], 1);
        atomicAdd(&degi[d4.w], 1);
    }
}

// =================== 2-level exclusive scan ===================
__global__ __launch_bounds__(256) void scan1(const int* __restrict__ degi, int* __restrict__ bsum)
{
    __shared__ int s[256];
    int base = blockIdx.x * 1024 + threadIdx.x * 4;
    int sum = 0;
    #pragma unroll
    for (int i = 0; i < 4; i++) { int n = base + i; if (n < Nn) sum += degi[n]; }
    s[threadIdx.x] = sum; __syncthreads();
    for (int o = 128; o; o >>= 1) {
        if (threadIdx.x < o) s[threadIdx.x] += s[threadIdx.x + o];
        __syncthreads();
    }
    if (threadIdx.x == 0) bsum[blockIdx.x] = s[0];
}

__global__ __launch_bounds__(256) void scan2(const int* __restrict__ bsum, int* __restrict__ bscan)
{
    __shared__ int s[256];
    int v = (threadIdx.x < NB1K) ? bsum[threadIdx.x] : 0;
    s[threadIdx.x] = v; __syncthreads();
    for (int o = 1; o < 256; o <<= 1) {
        int t = (threadIdx.x >= o) ? s[threadIdx.x - o] : 0;
        __syncthreads();
        s[threadIdx.x] += t;
        __syncthreads();
    }
    if (threadIdx.x < NB1K) bscan[threadIdx.x] = s[threadIdx.x] - v;  // exclusive
}

__global__ __launch_bounds__(256) void scan3(const int* __restrict__ degi, const int* __restrict__ bscan,
                                             int* __restrict__ off, int* __restrict__ cur)
{
    __shared__ int s[256];
    int tid = threadIdx.x;
    int base = blockIdx.x * 1024 + tid * 4;
    int d[4]; int sum = 0;
    #pragma unroll
    for (int i = 0; i < 4; i++) { int n = base + i; d[i] = (n < Nn) ? degi[n] : 0; sum += d[i]; }
    s[tid] = sum; __syncthreads();
    for (int o = 1; o < 256; o <<= 1) {
        int t = (tid >= o) ? s[tid - o] : 0;
        __syncthreads();
        s[tid] += t;
        __syncthreads();
    }
    int ex = s[tid] - sum + bscan[blockIdx.x];
    #pragma unroll
    for (int i = 0; i < 4; i++) {
        int n = base + i;
        if (n < Nn) { off[n] = ex; cur[n] = ex; ex += d[i]; }
    }
}

__global__ __launch_bounds__(256) void place_kernel(const int* __restrict__ src, const int* __restrict__ dst,
                                                    int* __restrict__ cur, int* __restrict__ csr)
{
    int t = blockIdx.x * blockDim.x + threadIdx.x;
    if (t < Ee / 4) {
        int4 s4 = reinterpret_cast<const int4*>(src)[t];
        int4 d4 = reinterpret_cast<const int4*>(dst)[t];
        int p;
        p = atomicAdd(&cur[d4.x], 1); csr[p] = s4.x;
        p = atomicAdd(&cur[d4.y], 1); csr[p] = s4.y;
        p = atomicAdd(&cur[d4.z], 1); csr[p] = s4.z;
        p = atomicAdd(&cur[d4.w], 1); csr[p] = s4.w;
    }
}

// =================== proj GEMM: h0 = relu(x @ Wp + bp), f32x2 ===================
#define XS_STRIDE 168
#define PROJ_SMEM ((IND * HID + 32 * XS_STRIDE) * 4)

__global__ __launch_bounds__(256) void proj_gemm(
    const float* __restrict__ x, const float* __restrict__ Wp,
    const float* __restrict__ bp, float* __restrict__ out)
{
    extern __shared__ float sm[];
    float* Ws = sm;                  // [IND][64]
    float* Xs = sm + IND * HID;      // [32][XS_STRIDE]
    const int t = threadIdx.x;
    for (int i = t; i < IND * HID; i += 256) Ws[i] = Wp[i];
    const int cg = t & 15;           // 16 col groups x 4 cols
    const int ng = t >> 4;           // 16 node groups x 2 nodes
    const int c0 = cg * 4;
    const u64 bias0 = packxy(bp[c0], bp[c0 + 1]);
    const u64 bias1 = packxy(bp[c0 + 2], bp[c0 + 3]);
    const ulonglong2* W2 = reinterpret_cast<const ulonglong2*>(Ws);  // [IND][16] ull2
    const int ntiles = Nn / 32;      // exact
    for (int tile = blockIdx.x; tile < ntiles; tile += gridDim.x) {
        const int n0 = tile * 32;
        __syncthreads();
        for (int i = t; i < 32 * IND; i += 256) {
            int node = i / IND;
            int c = i - node * IND;
            Xs[node * XS_STRIDE + c] = x[(size_t)(n0 + node) * IND + c];
        }
        __syncthreads();
        u64 acc[2][2];
        acc[0][0] = bias0; acc[0][1] = bias1;
        acc[1][0] = bias0; acc[1][1] = bias1;
        const float* xr0 = Xs + (ng * 2 + 0) * XS_STRIDE;
        const float* xr1 = Xs + (ng * 2 + 1) * XS_STRIDE;
        #pragma unroll 4
        for (int k4 = 0; k4 < IND / 4; k4++) {   // 41 iters
            float4 a0 = *reinterpret_cast<const float4*>(xr0 + k4 * 4);
            float4 a1 = *reinterpret_cast<const float4*>(xr1 + k4 * 4);
            #pragma unroll
            for (int kk = 0; kk < 4; kk++) {
                ulonglong2 w = W2[(k4 * 4 + kk) * 16 + cg];
                float av0 = (kk == 0) ? a0.x : (kk == 1) ? a0.y : (kk == 2) ? a0.z : a0.w;
                float av1 = (kk == 0) ? a1.x : (kk == 1) ? a1.y : (kk == 2) ? a1.z : a1.w;
                u64 p0 = pack2(av0), p1 = pack2(av1);
                acc[0][0] = fma2(p0, w.x, acc[0][0]);
                acc[0][1] = fma2(p0, w.y, acc[0][1]);
                acc[1][0] = fma2(p1, w.x, acc[1][0]);
                acc[1][1] = fma2(p1, w.y, acc[1][1]);
            }
        }
        {   // tail k = 164
            ulonglong2 w = W2[(IND - 1) * 16 + cg];
            u64 p0 = pack2(xr0[IND - 1]), p1 = pack2(xr1[IND - 1]);
            acc[0][0] = fma2(p0, w.x, acc[0][0]);
            acc[0][1] = fma2(p0, w.y, acc[0][1]);
            acc[1][0] = fma2(p1, w.x, acc[1][0]);
            acc[1][1] = fma2(p1, w.y, acc[1][1]);
        }
        #pragma unroll
        for (int i = 0; i < 2; i++) {
            int n = n0 + ng * 2 + i;
            float2 f0 = unpack2(acc[i][0]);
            float2 f1 = unpack2(acc[i][1]);
            float4 o;
            o.x = fmaxf(f0.x, 0.f); o.y = fmaxf(f0.y, 0.f);
            o.z = fmaxf(f1.x, 0.f); o.w = fmaxf(f1.y, 0.f);
            *reinterpret_cast<float4*>(out + (size_t)n * HID + c0) = o;
        }
    }
}

// ====== fused SAGE: gather-mean into smem, then GEMM (f32x2) ======
// As row layout: cols 0..63 = mean(neigh h), cols 64..127 = h[n]
// Ws rows 0..63 = Wl, 64..127 = Wr (matches As column order)
#define AS_STRIDE 132
#define SAGE_SMEM ((128 * HID + 64 * AS_STRIDE) * 4)

template<bool FINAL>
__global__ __launch_bounds__(256) void sage_fused(
    const float* __restrict__ h,
    const int* __restrict__ csr, const int* __restrict__ off, const int* __restrict__ degi,
    const float* __restrict__ Wl, const float* __restrict__ bl,
    const float* __restrict__ Wr, float* __restrict__ out,
    const float* __restrict__ Wc, const float* __restrict__ bc)
{
    extern __shared__ float sm[];
    float* Ws = sm;                  // [128][64]
    float* As = sm + 128 * HID;      // [64][AS_STRIDE]
    const int t = threadIdx.x;
    for (int i = t; i < HID * HID; i += 256) {
        Ws[i] = Wl[i];
        Ws[HID * HID + i] = Wr[i];
    }
    const int w = t >> 5;            // warp 0..7
    const int lane = t & 31;
    const int half = lane >> 4;
    const int q = lane & 15;
    // GEMM decomposition: 8 col-groups x 8 cols, 32 node-groups x 2 nodes
    const int cg = t & 7;
    const int ng = t >> 3;
    const int c0 = cg * 8;
    u64 bias[4];
    #pragma unroll
    for (int j = 0; j < 4; j++) bias[j] = packxy(bl[c0 + 2 * j], bl[c0 + 2 * j + 1]);
    float wcv[8]; float bc0 = 0.f;
    if (FINAL) {
        #pragma unroll
        for (int j = 0; j < 8; j++) wcv[j] = Wc[c0 + j];
        bc0 = bc[0];
    }
    const ulonglong2* W2 = reinterpret_cast<const ulonglong2*>(Ws);  // [128][16]
    const int ntiles = Nn / 64;      // exact (3125)
    for (int tile = blockIdx.x; tile < ntiles; tile += gridDim.x) {
        const int n0 = tile * 64;
        __syncthreads();
        // ---- gather phase: warp per node, 8 nodes per warp ----
        #pragma unroll 1
        for (int i = 0; i < 8; i++) {
            const int nl = w + 8 * i;
            const int n = n0 + nl;
            // h row (for the self/Wr half) loaded by half 1
            float4 hv;
            if (half) hv = *reinterpret_cast<const float4*>(h + (size_t)n * HID + q * 4);
            const int beg = off[n];
            const int d = degi[n];
            const int* cp = csr + beg;
            float4 acc = make_float4(0.f, 0.f, 0.f, 0.f);
            int e = half;
            for (; e + 6 < d; e += 8) {
                int s0 = __ldg(&cp[e]);
                int s1 = __ldg(&cp[e + 2]);
                int s2 = __ldg(&cp[e + 4]);
                int s3 = __ldg(&cp[e + 6]);
                float4 v0 = *reinterpret_cast<const float4*>(h + (size_t)s0 * HID + q * 4);
                float4 v1 = *reinterpret_cast<const float4*>(h + (size_t)s1 * HID + q * 4);
                float4 v2 = *reinterpret_cast<const float4*>(h + (size_t)s2 * HID + q * 4);
                float4 v3 = *reinterpret_cast<const float4*>(h + (size_t)s3 * HID + q * 4);
                acc.x += (v0.x + v1.x) + (v2.x + v3.x);
                acc.y += (v0.y + v1.y) + (v2.y + v3.y);
                acc.z += (v0.z + v1.z) + (v2.z + v3.z);
                acc.w += (v0.w + v1.w) + (v2.w + v3.w);
            }
            for (; e < d; e += 2) {
                int s = __ldg(&cp[e]);
                float4 v = *reinterpret_cast<const float4*>(h + (size_t)s * HID + q * 4);
                acc.x += v.x; acc.y += v.y; acc.z += v.z; acc.w += v.w;
            }
            acc.x += __shfl_xor_sync(0xffffffffu, acc.x, 16);
            acc.y += __shfl_xor_sync(0xffffffffu, acc.y, 16);
            acc.z += __shfl_xor_sync(0xffffffffu, acc.z, 16);
            acc.w += __shfl_xor_sync(0xffffffffu, acc.w, 16);
            if (half == 0) {
                float inv = 1.0f / fmaxf((float)d, 1.0f);
                acc.x *= inv; acc.y *= inv; acc.z *= inv; acc.w *= inv;
                *reinterpret_cast<float4*>(As + nl * AS_STRIDE + q * 4) = acc;
            } else {
                *reinterpret_cast<float4*>(As + nl * AS_STRIDE + HID + q * 4) = hv;
            }
        }
        __syncthreads();
        // ---- GEMM phase ----
        u64 acc[2][4];
        #pragma unroll
        for (int j = 0; j < 4; j++) { acc[0][j] = bias[j]; acc[1][j] = bias[j]; }
        const float* ar0 = As + (ng * 2 + 0) * AS_STRIDE;
        const float* ar1 = As + (ng * 2 + 1) * AS_STRIDE;
        #pragma unroll 2
        for (int k4 = 0; k4 < 32; k4++) {
            float4 a0 = *reinterpret_cast<const float4*>(ar0 + k4 * 4);
            float4 a1 = *reinterpret_cast<const float4*>(ar1 + k4 * 4);
            #pragma unroll
            for (int kk = 0; kk < 4; kk++) {
                const int k = k4 * 4 + kk;
                ulonglong2 wA = W2[k * 16 + cg * 2 + 0];
                ulonglong2 wB = W2[k * 16 + cg * 2 + 1];
                float av0 = (kk == 0) ? a0.x : (kk == 1) ? a0.y : (kk == 2) ? a0.z : a0.w;
                float av1 = (kk == 0) ? a1.x : (kk == 1) ? a1.y : (kk == 2) ? a1.z : a1.w;
                u64 p0 = pack2(av0), p1 = pack2(av1);
                acc[0][0] = fma2(p0, wA.x, acc[0][0]);
                acc[0][1] = fma2(p0, wA.y, acc[0][1]);
                acc[0][2] = fma2(p0, wB.x, acc[0][2]);
                acc[0][3] = fma2(p0, wB.y, acc[0][3]);
                acc[1][0] = fma2(p1, wA.x, acc[1][0]);
                acc[1][1] = fma2(p1, wA.y, acc[1][1]);
                acc[1][2] = fma2(p1, wB.x, acc[1][2]);
                acc[1][3] = fma2(p1, wB.y, acc[1][3]);
            }
        }
        if (FINAL) {
            #pragma unroll
            for (int i = 0; i < 2; i++) {
                float part = 0.f;
                #pragma unroll
                for (int j = 0; j < 4; j++) {
                    float2 f = unpack2(acc[i][j]);
                    part = fmaf(fmaxf(f.x, 0.f), wcv[2 * j], part);
                    part = fmaf(fmaxf(f.y, 0.f), wcv[2 * j + 1], part);
                }
                part += __shfl_xor_sync(0xffffffffu, part, 1);
                part += __shfl_xor_sync(0xffffffffu, part, 2);
                part += __shfl_xor_sync(0xffffffffu, part, 4);
                if (cg == 0) out[n0 + ng * 2 + i] = part + bc0;
            }
        } else {
            #pragma unroll
            for (int i = 0; i < 2; i++) {
                const int n = n0 + ng * 2 + i;
                float4 o0, o1;
                float2 f;
                f = unpack2(acc[i][0]); o0.x = fmaxf(f.x, 0.f); o0.y = fmaxf(f.y, 0.f);
                f = unpack2(acc[i][1]); o0.z = fmaxf(f.x, 0.f); o0.w = fmaxf(f.y, 0.f);
                f = unpack2(acc[i][2]); o1.x = fmaxf(f.x, 0.f); o1.y = fmaxf(f.y, 0.f);
                f = unpack2(acc[i][3]); o1.z = fmaxf(f.x, 0.f); o1.w = fmaxf(f.y, 0.f);
                *reinterpret_cast<float4*>(out + (size_t)n * HID + c0) = o0;
                *reinterpret_cast<float4*>(out + (size_t)n * HID + c0 + 4) = o1;
            }
        }
    }
}

extern "C" void kernel_launch(void* const* d_in, const int* in_sizes, int n_in,
                              void* d_out, int out_size)
{
    const float* x   = (const float*)d_in[0];
    const int*   ei  = (const int*)d_in[1];
    const float* Wp  = (const float*)d_in[2];
    const float* bp  = (const float*)d_in[3];
    const float* W1l = (const float*)d_in[4];
    const float* b1l = (const float*)d_in[5];
    const float* W1r = (const float*)d_in[6];
    const float* W2l = (const float*)d_in[7];
    const float* b2l = (const float*)d_in[8];
    const float* W2r = (const float*)d_in[9];
    const float* Wc  = (const float*)d_in[10];
    const float* bc  = (const float*)d_in[11];
    float* out = (float*)d_out;

    const int* src = ei;
    const int* dst = ei + Ee;

    float *h0, *h1;
    int *degi, *off, *cur, *csr, *bsum, *bscan;
    cudaGetSymbolAddress((void**)&h0, g_h0);
    cudaGetSymbolAddress((void**)&h1, g_h1);
    cudaGetSymbolAddress((void**)&degi, g_degi);
    cudaGetSymbolAddress((void**)&off, g_off);
    cudaGetSymbolAddress((void**)&cur, g_cur);
    cudaGetSymbolAddress((void**)&csr, g_csr);
    cudaGetSymbolAddress((void**)&bsum, g_bsum);
    cudaGetSymbolAddress((void**)&bscan, g_bscan);

    static cudaStream_t s2 = nullptr;
    static cudaEvent_t evFork = nullptr, evJoin = nullptr;
    if (!s2) {
        cudaStreamCreateWithFlags(&s2, cudaStreamNonBlocking);
        cudaEventCreateWithFlags(&evFork, cudaEventDisableTiming);
        cudaEventCreateWithFlags(&evJoin, cudaEventDisableTiming);
        cudaFuncSetAttribute(proj_gemm, cudaFuncAttributeMaxDynamicSharedMemorySize, PROJ_SMEM);
        cudaFuncSetAttribute(sage_fused<false>, cudaFuncAttributeMaxDynamicSharedMemorySize, SAGE_SMEM);
        cudaFuncSetAttribute(sage_fused<true>, cudaFuncAttributeMaxDynamicSharedMemorySize, SAGE_SMEM);
    }

    // ---- fork: CSR build on side stream, proj on main stream ----
    cudaEventRecord(evFork, 0);
    cudaStreamWaitEvent(s2, evFork, 0);

    cudaMemsetAsync(degi, 0, Nn * sizeof(int), s2);
    deg_kernel<<<(Ee / 4 + 255) / 256, 256, 0, s2>>>(dst, degi);
    scan1<<<NB1K, 256, 0, s2>>>(degi, bsum);
    scan2<<<1, 256, 0, s2>>>(bsum, bscan);
    scan3<<<NB1K, 256, 0, s2>>>(degi, bscan, off, cur);
    place_kernel<<<(Ee / 4 + 255) / 256, 256, 0, s2>>>(src, dst, cur, csr);
    cudaEventRecord(evJoin, s2);

    proj_gemm<<<444, 256, PROJ_SMEM>>>(x, Wp, bp, h0);

    // ---- join ----
    cudaStreamWaitEvent(0, evJoin, 0);

    // ---- layer 1 (fused gather + GEMM) ----
    sage_fused<false><<<444, 256, SAGE_SMEM>>>(h0, csr, off, degi, W1l, b1l, W1r, h1, nullptr, nullptr);

    // ---- layer 2 (fused gather + GEMM + classifier) ----
    sage_fused<true><<<444, 256, SAGE_SMEM>>>(h1, csr, off, degi, W2l, b2l, W2r, out, Wc, bc);
}

// round 7
// speedup vs baseline: 1.0359x; 1.0359x over previous
#include <cuda_runtime.h>

#define Nn 200000
#define Ee 3200000
#define IND 165
#define HID 64
#define NB1K 196   // ceil(Nn/1024)

// ---- scratch (no cudaMalloc allowed) ----
__device__ float g_h0[Nn * HID];
__device__ float g_h1[Nn * HID];
__device__ float g_aggr[Nn * HID];
__device__ int   g_degi[Nn];
__device__ int   g_off[Nn];
__device__ int   g_cur[Nn];
__device__ int   g_csr[Ee];
__device__ int   g_bsum[256];
__device__ int   g_bscan[256];

// ---- packed f32x2 helpers (sm_103a) ----
typedef unsigned long long u64;
__device__ __forceinline__ u64 pack2(float v) {
    u64 r; asm("mov.b64 %0, {%1, %1};" : "=l"(r) : "f"(v)); return r;
}
__device__ __forceinline__ u64 packxy(float x, float y) {
    u64 r; asm("mov.b64 %0, {%1, %2};" : "=l"(r) : "f"(x), "f"(y)); return r;
}
__device__ __forceinline__ u64 fma2(u64 a, u64 b, u64 c) {
    u64 d; asm("fma.rn.f32x2 %0, %1, %2, %3;" : "=l"(d) : "l"(a), "l"(b), "l"(c)); return d;
}
__device__ __forceinline__ float2 unpack2(u64 v) {
    float2 f; asm("mov.b64 {%0, %1}, %2;" : "=f"(f.x), "=f"(f.y) : "l"(v)); return f;
}

// =================== degree histogram (int4) ===================
__global__ __launch_bounds__(256) void deg_kernel(const int* __restrict__ dst, int* __restrict__ degi)
{
    int t = blockIdx.x * blockDim.x + threadIdx.x;
    if (t < Ee / 4) {
        int4 d4 = reinterpret_cast<const int4*>(dst)[t];
        atomicAdd(&degi[d4.x], 1);
        atomicAdd(&degi[d4.y], 1);
        atomicAdd(&degi[d4.z], 1);
        atomicAdd(&degi[d4.w], 1);
    }
}

// =================== 2-level exclusive scan ===================
__global__ __launch_bounds__(256) void scan1(const int* __restrict__ degi, int* __restrict__ bsum)
{
    __shared__ int s[256];
    int base = blockIdx.x * 1024 + threadIdx.x * 4;
    int sum = 0;
    #pragma unroll
    for (int i = 0; i < 4; i++) { int n = base + i; if (n < Nn) sum += degi[n]; }
    s[threadIdx.x] = sum; __syncthreads();
    for (int o = 128; o; o >>= 1) {
        if (threadIdx.x < o) s[threadIdx.x] += s[threadIdx.x + o];
        __syncthreads();
    }
    if (threadIdx.x == 0) bsum[blockIdx.x] = s[0];
}

__global__ __launch_bounds__(256) void scan2(const int* __restrict__ bsum, int* __restrict__ bscan)
{
    __shared__ int s[256];
    int v = (threadIdx.x < NB1K) ? bsum[threadIdx.x] : 0;
    s[threadIdx.x] = v; __syncthreads();
    for (int o = 1; o < 256; o <<= 1) {
        int t = (threadIdx.x >= o) ? s[threadIdx.x - o] : 0;
        __syncthreads();
        s[threadIdx.x] += t;
        __syncthreads();
    }
    if (threadIdx.x < NB1K) bscan[threadIdx.x] = s[threadIdx.x] - v;  // exclusive
}

__global__ __launch_bounds__(256) void scan3(const int* __restrict__ degi, const int* __restrict__ bscan,
                                             int* __restrict__ off, int* __restrict__ cur)
{
    __shared__ int s[256];
    int tid = threadIdx.x;
    int base = blockIdx.x * 1024 + tid * 4;
    int d[4]; int sum = 0;
    #pragma unroll
    for (int i = 0; i < 4; i++) { int n = base + i; d[i] = (n < Nn) ? degi[n] : 0; sum += d[i]; }
    s[tid] = sum; __syncthreads();
    for (int o = 1; o < 256; o <<= 1) {
        int t = (tid >= o) ? s[tid - o] : 0;
        __syncthreads();
        s[tid] += t;
        __syncthreads();
    }
    int ex = s[tid] - sum + bscan[blockIdx.x];
    #pragma unroll
    for (int i = 0; i < 4; i++) {
        int n = base + i;
        if (n < Nn) { off[n] = ex; cur[n] = ex; ex += d[i]; }
    }
}

__global__ __launch_bounds__(256) void place_kernel(const int* __restrict__ src, const int* __restrict__ dst,
                                                    int* __restrict__ cur, int* __restrict__ csr)
{
    int t = blockIdx.x * blockDim.x + threadIdx.x;
    if (t < Ee / 4) {
        int4 s4 = reinterpret_cast<const int4*>(src)[t];
        int4 d4 = reinterpret_cast<const int4*>(dst)[t];
        int p;
        p = atomicAdd(&cur[d4.x], 1); csr[p] = s4.x;
        p = atomicAdd(&cur[d4.y], 1); csr[p] = s4.y;
        p = atomicAdd(&cur[d4.z], 1); csr[p] = s4.z;
        p = atomicAdd(&cur[d4.w], 1); csr[p] = s4.w;
    }
}

// =================== gather-mean (warp per node, MLP-unrolled) ===================
__global__ __launch_bounds__(256) void gather_mean(
    const int* __restrict__ csr, const int* __restrict__ off, const int* __restrict__ degi,
    const float* __restrict__ h, float* __restrict__ aggr)
{
    long long t = (long long)blockIdx.x * blockDim.x + threadIdx.x;
    int node = (int)(t >> 5);
    if (node >= Nn) return;
    int lane = threadIdx.x & 31;
    int half = lane >> 4;      // 0/1 : alternates edges
    int q = lane & 15;         // float4 slot (cols q*4..q*4+3)
    const int beg = off[node];
    const int d = degi[node];
    const int* cp = csr + beg;
    float4 acc = make_float4(0.f, 0.f, 0.f, 0.f);
    int i = half;
    for (; i + 6 < d; i += 8) {
        int s0 = __ldg(&cp[i]);
        int s1 = __ldg(&cp[i + 2]);
        int s2 = __ldg(&cp[i + 4]);
        int s3 = __ldg(&cp[i + 6]);
        float4 v0 = *reinterpret_cast<const float4*>(h + (size_t)s0 * HID + q * 4);
        float4 v1 = *reinterpret_cast<const float4*>(h + (size_t)s1 * HID + q * 4);
        float4 v2 = *reinterpret_cast<const float4*>(h + (size_t)s2 * HID + q * 4);
        float4 v3 = *reinterpret_cast<const float4*>(h + (size_t)s3 * HID + q * 4);
        acc.x += (v0.x + v1.x) + (v2.x + v3.x);
        acc.y += (v0.y + v1.y) + (v2.y + v3.y);
        acc.z += (v0.z + v1.z) + (v2.z + v3.z);
        acc.w += (v0.w + v1.w) + (v2.w + v3.w);
    }
    for (; i < d; i += 2) {
        int s = __ldg(&cp[i]);
        float4 v = *reinterpret_cast<const float4*>(h + (size_t)s * HID + q * 4);
        acc.x += v.x; acc.y += v.y; acc.z += v.z; acc.w += v.w;
    }
    acc.x += __shfl_xor_sync(0xffffffffu, acc.x, 16);
    acc.y += __shfl_xor_sync(0xffffffffu, acc.y, 16);
    acc.z += __shfl_xor_sync(0xffffffffu, acc.z, 16);
    acc.w += __shfl_xor_sync(0xffffffffu, acc.w, 16);
    if (half == 0) {
        float inv = 1.0f / fmaxf((float)d, 1.0f);
        acc.x *= inv; acc.y *= inv; acc.z *= inv; acc.w *= inv;
        *reinterpret_cast<float4*>(aggr + (size_t)node * HID + q * 4) = acc;
    }
}

// =================== proj GEMM: h0 = relu(x @ Wp + bp), f32x2 ===================
#define XS_STRIDE 168
#define PROJ_SMEM ((IND * HID + 32 * XS_STRIDE) * 4)

__global__ __launch_bounds__(256) void proj_gemm(
    const float* __restrict__ x, const float* __restrict__ Wp,
    const float* __restrict__ bp, float* __restrict__ out)
{
    extern __shared__ float sm[];
    float* Ws = sm;                  // [IND][64]
    float* Xs = sm + IND * HID;      // [32][XS_STRIDE]
    const int t = threadIdx.x;
    for (int i = t; i < IND * HID; i += 256) Ws[i] = Wp[i];
    const int cg = t & 15;           // 16 col groups x 4 cols
    const int ng = t >> 4;           // 16 node groups x 2 nodes
    const int c0 = cg * 4;
    const u64 bias0 = packxy(bp[c0], bp[c0 + 1]);
    const u64 bias1 = packxy(bp[c0 + 2], bp[c0 + 3]);
    const ulonglong2* W2 = reinterpret_cast<const ulonglong2*>(Ws);  // [IND][16]
    const int ntiles = Nn / 32;      // exact
    for (int tile = blockIdx.x; tile < ntiles; tile += gridDim.x) {
        const int n0 = tile * 32;
        __syncthreads();
        for (int i = t; i < 32 * IND; i += 256) {
            int node = i / IND;
            int c = i - node * IND;
            Xs[node * XS_STRIDE + c] = x[(size_t)(n0 + node) * IND + c];
        }
        __syncthreads();
        u64 acc[2][2];
        acc[0][0] = bias0; acc[0][1] = bias1;
        acc[1][0] = bias0; acc[1][1] = bias1;
        const float* xr0 = Xs + (ng * 2 + 0) * XS_STRIDE;
        const float* xr1 = Xs + (ng * 2 + 1) * XS_STRIDE;
        #pragma unroll 4
        for (int k4 = 0; k4 < IND / 4; k4++) {   // 41 iters
            float4 a0 = *reinterpret_cast<const float4*>(xr0 + k4 * 4);
            float4 a1 = *reinterpret_cast<const float4*>(xr1 + k4 * 4);
            #pragma unroll
            for (int kk = 0; kk < 4; kk++) {
                ulonglong2 w = W2[(k4 * 4 + kk) * 16 + cg];
                float av0 = (kk == 0) ? a0.x : (kk == 1) ? a0.y : (kk == 2) ? a0.z : a0.w;
                float av1 = (kk == 0) ? a1.x : (kk == 1) ? a1.y : (kk == 2) ? a1.z : a1.w;
                u64 p0 = pack2(av0), p1 = pack2(av1);
                acc[0][0] = fma2(p0, w.x, acc[0][0]);
                acc[0][1] = fma2(p0, w.y, acc[0][1]);
                acc[1][0] = fma2(p1, w.x, acc[1][0]);
                acc[1][1] = fma2(p1, w.y, acc[1][1]);
            }
        }
        {   // tail k = 164
            ulonglong2 w = W2[(IND - 1) * 16 + cg];
            u64 p0 = pack2(xr0[IND - 1]), p1 = pack2(xr1[IND - 1]);
            acc[0][0] = fma2(p0, w.x, acc[0][0]);
            acc[0][1] = fma2(p0, w.y, acc[0][1]);
            acc[1][0] = fma2(p1, w.x, acc[1][0]);
            acc[1][1] = fma2(p1, w.y, acc[1][1]);
        }
        #pragma unroll
        for (int i = 0; i < 2; i++) {
            int n = n0 + ng * 2 + i;
            float2 f0 = unpack2(acc[i][0]);
            float2 f1 = unpack2(acc[i][1]);
            float4 o;
            o.x = fmaxf(f0.x, 0.f); o.y = fmaxf(f0.y, 0.f);
            o.z = fmaxf(f1.x, 0.f); o.w = fmaxf(f1.y, 0.f);
            *reinterpret_cast<float4*>(out + (size_t)n * HID + c0) = o;
        }
    }
}

// ====== SAGE GEMM: out = relu([aggr | h] @ [Wl ; Wr] + bl), f32x2 ======
// FINAL=true fuses the classifier: out[n] = relu(row) . Wc + bc
#define AS_STRIDE 132
#define SAGE_SMEM ((128 * HID + 64 * AS_STRIDE) * 4)

template<bool FINAL>
__global__ __launch_bounds__(256) void sage_gemm(
    const float* __restrict__ h, const float* __restrict__ aggr,
    const float* __restrict__ Wl, const float* __restrict__ bl,
    const float* __restrict__ Wr, float* __restrict__ out,
    const float* __restrict__ Wc, const float* __restrict__ bc)
{
    extern __shared__ float sm[];
    float* Ws = sm;                  // [128][64]: rows 0-63 Wl, 64-127 Wr
    float* As = sm + 128 * HID;      // [64][AS_STRIDE]
    const int t = threadIdx.x;
    for (int i = t; i < HID * HID; i += 256) {
        Ws[i] = Wl[i];
        Ws[HID * HID + i] = Wr[i];
    }
    // GEMM decomposition: 8 col-groups x 8 cols, 32 node-groups x 2 nodes
    const int cg = t & 7;
    const int ng = t >> 3;
    const int c0 = cg * 8;
    u64 bias[4];
    #pragma unroll
    for (int j = 0; j < 4; j++) bias[j] = packxy(bl[c0 + 2 * j], bl[c0 + 2 * j + 1]);
    float wcv[8]; float bc0 = 0.f;
    if (FINAL) {
        #pragma unroll
        for (int j = 0; j < 8; j++) wcv[j] = Wc[c0 + j];
        bc0 = bc[0];
    }
    const ulonglong2* W2 = reinterpret_cast<const ulonglong2*>(Ws);  // [128][16]
    const int ntiles = Nn / 64;      // 3125
    for (int tile = blockIdx.x; tile < ntiles; tile += gridDim.x) {
        const int n0 = tile * 64;
        __syncthreads();
        for (int i = t; i < 64 * 32; i += 256) {
            int node = i >> 5;
            int p = i & 31;
            int n = n0 + node;
            float4 v = (p < 16) ? *reinterpret_cast<const float4*>(aggr + (size_t)n * HID + p * 4)
                                : *reinterpret_cast<const float4*>(h + (size_t)n * HID + (p - 16) * 4);
            *reinterpret_cast<float4*>(As + node * AS_STRIDE + p * 4) = v;
        }
        __syncthreads();
        u64 acc[2][4];
        #pragma unroll
        for (int j = 0; j < 4; j++) { acc[0][j] = bias[j]; acc[1][j] = bias[j]; }
        const float* ar0 = As + (ng * 2 + 0) * AS_STRIDE;
        const float* ar1 = As + (ng * 2 + 1) * AS_STRIDE;
        #pragma unroll 2
        for (int k4 = 0; k4 < 32; k4++) {
            float4 a0 = *reinterpret_cast<const float4*>(ar0 + k4 * 4);
            float4 a1 = *reinterpret_cast<const float4*>(ar1 + k4 * 4);
            #pragma unroll
            for (int kk = 0; kk < 4; kk++) {
                const int k = k4 * 4 + kk;
                ulonglong2 wA = W2[k * 16 + cg * 2 + 0];
                ulonglong2 wB = W2[k * 16 + cg * 2 + 1];
                float av0 = (kk == 0) ? a0.x : (kk == 1) ? a0.y : (kk == 2) ? a0.z : a0.w;
                float av1 = (kk == 0) ? a1.x : (kk == 1) ? a1.y : (kk == 2) ? a1.z : a1.w;
                u64 p0 = pack2(av0), p1 = pack2(av1);
                acc[0][0] = fma2(p0, wA.x, acc[0][0]);
                acc[0][1] = fma2(p0, wA.y, acc[0][1]);
                acc[0][2] = fma2(p0, wB.x, acc[0][2]);
                acc[0][3] = fma2(p0, wB.y, acc[0][3]);
                acc[1][0] = fma2(p1, wA.x, acc[1][0]);
                acc[1][1] = fma2(p1, wA.y, acc[1][1]);
                acc[1][2] = fma2(p1, wB.x, acc[1][2]);
                acc[1][3] = fma2(p1, wB.y, acc[1][3]);
            }
        }
        if (FINAL) {
            #pragma unroll
            for (int i = 0; i < 2; i++) {
                float part = 0.f;
                #pragma unroll
                for (int j = 0; j < 4; j++) {
                    float2 f = unpack2(acc[i][j]);
                    part = fmaf(fmaxf(f.x, 0.f), wcv[2 * j], part);
                    part = fmaf(fmaxf(f.y, 0.f), wcv[2 * j + 1], part);
                }
                part += __shfl_xor_sync(0xffffffffu, part, 1);
                part += __shfl_xor_sync(0xffffffffu, part, 2);
                part += __shfl_xor_sync(0xffffffffu, part, 4);
                if (cg == 0) out[n0 + ng * 2 + i] = part + bc0;
            }
        } else {
            #pragma unroll
            for (int i = 0; i < 2; i++) {
                const int n = n0 + ng * 2 + i;
                float4 o0, o1;
                float2 f;
                f = unpack2(acc[i][0]); o0.x = fmaxf(f.x, 0.f); o0.y = fmaxf(f.y, 0.f);
                f = unpack2(acc[i][1]); o0.z = fmaxf(f.x, 0.f); o0.w = fmaxf(f.y, 0.f);
                f = unpack2(acc[i][2]); o1.x = fmaxf(f.x, 0.f); o1.y = fmaxf(f.y, 0.f);
                f = unpack2(acc[i][3]); o1.z = fmaxf(f.x, 0.f); o1.w = fmaxf(f.y, 0.f);
                *reinterpret_cast<float4*>(out + (size_t)n * HID + c0) = o0;
                *reinterpret_cast<float4*>(out + (size_t)n * HID + c0 + 4) = o1;
            }
        }
    }
}

extern "C" void kernel_launch(void* const* d_in, const int* in_sizes, int n_in,
                              void* d_out, int out_size)
{
    const float* x   = (const float*)d_in[0];
    const int*   ei  = (const int*)d_in[1];
    const float* Wp  = (const float*)d_in[2];
    const float* bp  = (const float*)d_in[3];
    const float* W1l = (const float*)d_in[4];
    const float* b1l = (const float*)d_in[5];
    const float* W1r = (const float*)d_in[6];
    const float* W2l = (const float*)d_in[7];
    const float* b2l = (const float*)d_in[8];
    const float* W2r = (const float*)d_in[9];
    const float* Wc  = (const float*)d_in[10];
    const float* bc  = (const float*)d_in[11];
    float* out = (float*)d_out;

    const int* src = ei;
    const int* dst = ei + Ee;

    float *h0, *h1, *aggr;
    int *degi, *off, *cur, *csr, *bsum, *bscan;
    cudaGetSymbolAddress((void**)&h0, g_h0);
    cudaGetSymbolAddress((void**)&h1, g_h1);
    cudaGetSymbolAddress((void**)&aggr, g_aggr);
    cudaGetSymbolAddress((void**)&degi, g_degi);
    cudaGetSymbolAddress((void**)&off, g_off);
    cudaGetSymbolAddress((void**)&cur, g_cur);
    cudaGetSymbolAddress((void**)&csr, g_csr);
    cudaGetSymbolAddress((void**)&bsum, g_bsum);
    cudaGetSymbolAddress((void**)&bscan, g_bscan);

    static cudaStream_t s2 = nullptr;
    static cudaEvent_t evFork = nullptr, evJoin = nullptr;
    if (!s2) {
        cudaStreamCreateWithFlags(&s2, cudaStreamNonBlocking);
        cudaEventCreateWithFlags(&evFork, cudaEventDisableTiming);
        cudaEventCreateWithFlags(&evJoin, cudaEventDisableTiming);
        cudaFuncSetAttribute(proj_gemm, cudaFuncAttributeMaxDynamicSharedMemorySize, PROJ_SMEM);
        cudaFuncSetAttribute(sage_gemm<false>, cudaFuncAttributeMaxDynamicSharedMemorySize, SAGE_SMEM);
        cudaFuncSetAttribute(sage_gemm<true>, cudaFuncAttributeMaxDynamicSharedMemorySize, SAGE_SMEM);
    }

    // ---- fork: CSR build on side stream, proj on main stream ----
    cudaEventRecord(evFork, 0);
    cudaStreamWaitEvent(s2, evFork, 0);

    cudaMemsetAsync(degi, 0, Nn * sizeof(int), s2);
    deg_kernel<<<(Ee / 4 + 255) / 256, 256, 0, s2>>>(dst, degi);
    scan1<<<NB1K, 256, 0, s2>>>(degi, bsum);
    scan2<<<1, 256, 0, s2>>>(bsum, bscan);
    scan3<<<NB1K, 256, 0, s2>>>(degi, bscan, off, cur);
    place_kernel<<<(Ee / 4 + 255) / 256, 256, 0, s2>>>(src, dst, cur, csr);
    cudaEventRecord(evJoin, s2);

    proj_gemm<<<444, 256, PROJ_SMEM>>>(x, Wp, bp, h0);

    // ---- join ----
    cudaStreamWaitEvent(0, evJoin, 0);

    // ---- layer 1 ----
    gather_mean<<<(Nn * 32 + 255) / 256, 256>>>(csr, off, degi, h0, aggr);
    sage_gemm<false><<<444, 256, SAGE_SMEM>>>(h0, aggr, W1l, b1l, W1r, h1, nullptr, nullptr);

    // ---- layer 2 (+ fused classifier) ----
    gather_mean<<<(Nn * 32 + 255) / 256, 256>>>(csr, off, degi, h1, aggr);
    sage_gemm<true><<<444, 256, SAGE_SMEM>>>(h1, aggr, W2l, b2l, W2r, out, Wc, bc);
}

// round 9
// speedup vs baseline: 1.5468x; 1.4932x over previous
#include <cuda_runtime.h>
#include <cuda_fp16.h>

#define Nn 200000
#define Ee 3200000
#define IND 165
#define HID 64
#define NB1K 196   // ceil(Nn/1024)

// ---- scratch (no cudaMalloc allowed) ----
__device__ float g_h0[Nn * HID];
__device__ float g_h1[Nn * HID];
__device__ float g_aggr[Nn * HID];
__device__ uint4 g_hh0[Nn * 8];   // fp16 mirror of h0 (64 halves = 8 uint4 per row)
__device__ uint4 g_hh1[Nn * 8];   // fp16 mirror of h1
__device__ int   g_degi[Nn];
__device__ int   g_off[Nn];
__device__ int   g_cur[Nn];
__device__ int   g_csr[Ee];
__device__ int   g_bsum[256];
__device__ int   g_bscan[256];

__device__ __forceinline__ unsigned h2u(__half2 h) {
    return *reinterpret_cast<unsigned*>(&h);
}

// =================== degree histogram (int4) ===================
__global__ __launch_bounds__(256) void deg_kernel(const int* __restrict__ dst, int* __restrict__ degi)
{
    int t = blockIdx.x * blockDim.x + threadIdx.x;
    if (t < Ee / 4) {
        int4 d4 = reinterpret_cast<const int4*>(dst)[t];
        atomicAdd(&degi[d4.x], 1);
        atomicAdd(&degi[d4.y], 1);
        atomicAdd(&degi[d4.z], 1);
        atomicAdd(&degi[d4.w], 1);
    }
}

// =================== 2-level exclusive scan ===================
__global__ __launch_bounds__(256) void scan1(const int* __restrict__ degi, int* __restrict__ bsum)
{
    __shared__ int s[256];
    int base = blockIdx.x * 1024 + threadIdx.x * 4;
    int sum = 0;
    #pragma unroll
    for (int i = 0; i < 4; i++) { int n = base + i; if (n < Nn) sum += degi[n]; }
    s[threadIdx.x] = sum; __syncthreads();
    for (int o = 128; o; o >>= 1) {
        if (threadIdx.x < o) s[threadIdx.x] += s[threadIdx.x + o];
        __syncthreads();
    }
    if (threadIdx.x == 0) bsum[blockIdx.x] = s[0];
}

__global__ __launch_bounds__(256) void scan2(const int* __restrict__ bsum, int* __restrict__ bscan)
{
    __shared__ int s[256];
    int v = (threadIdx.x < NB1K) ? bsum[threadIdx.x] : 0;
    s[threadIdx.x] = v; __syncthreads();
    for (int o = 1; o < 256; o <<= 1) {
        int t = (threadIdx.x >= o) ? s[threadIdx.x - o] : 0;
        __syncthreads();
        s[threadIdx.x] += t;
        __syncthreads();
    }
    if (threadIdx.x < NB1K) bscan[threadIdx.x] = s[threadIdx.x] - v;  // exclusive
}

__global__ __launch_bounds__(256) void scan3(const int* __restrict__ degi, const int* __restrict__ bscan,
                                             int* __restrict__ off, int* __restrict__ cur)
{
    __shared__ int s[256];
    int tid = threadIdx.x;
    int base = blockIdx.x * 1024 + tid * 4;
    int d[4]; int sum = 0;
    #pragma unroll
    for (int i = 0; i < 4; i++) { int n = base + i; d[i] = (n < Nn) ? degi[n] : 0; sum += d[i]; }
    s[tid] = sum; __syncthreads();
    for (int o = 1; o < 256; o <<= 1) {
        int t = (tid >= o) ? s[tid - o] : 0;
        __syncthreads();
        s[tid] += t;
        __syncthreads();
    }
    int ex = s[tid] - sum + bscan[blockIdx.x];
    #pragma unroll
    for (int i = 0; i < 4; i++) {
        int n = base + i;
        if (n < Nn) { off[n] = ex; cur[n] = ex; ex += d[i]; }
    }
}

__global__ __launch_bounds__(256) void place_kernel(const int* __restrict__ src, const int* __restrict__ dst,
                                                    int* __restrict__ cur, int* __restrict__ csr)
{
    int t = blockIdx.x * blockDim.x + threadIdx.x;
    if (t < Ee / 4) {
        int4 s4 = reinterpret_cast<const int4*>(src)[t];
        int4 d4 = reinterpret_cast<const int4*>(dst)[t];
        int p;
        p = atomicAdd(&cur[d4.x], 1); csr[p] = s4.x;
        p = atomicAdd(&cur[d4.y], 1); csr[p] = s4.y;
        p = atomicAdd(&cur[d4.z], 1); csr[p] = s4.z;
        p = atomicAdd(&cur[d4.w], 1); csr[p] = s4.w;
    }
}

// ======== gather-mean from fp16 rows (warp per node, 4 edge-slots x 8 lanes) ========
__device__ __forceinline__ void acc_u4(const uint4& v, float2& a0, float2& a1, float2& a2, float2& a3)
{
    float2 f;
    f = __half22float2(*reinterpret_cast<const __half2*>(&v.x)); a0.x += f.x; a0.y += f.y;
    f = __half22float2(*reinterpret_cast<const __half2*>(&v.y)); a1.x += f.x; a1.y += f.y;
    f = __half22float2(*reinterpret_cast<const __half2*>(&v.z)); a2.x += f.x; a2.y += f.y;
    f = __half22float2(*reinterpret_cast<const __half2*>(&v.w)); a3.x += f.x; a3.y += f.y;
}

__global__ __launch_bounds__(256) void gather_mean_h(
    const int* __restrict__ csr, const int* __restrict__ off, const int* __restrict__ degi,
    const uint4* __restrict__ hh, float* __restrict__ aggr)
{
    int node = (int)((blockIdx.x * (unsigned)blockDim.x + threadIdx.x) >> 5);
    if (node >= Nn) return;
    const int lane = threadIdx.x & 31;
    const int slot = lane >> 3;   // 0..3 : edge slot
    const int q = lane & 7;       // 16-byte chunk (cols 8q..8q+7)
    const int beg = off[node];
    const int d = degi[node];
    const int* cp = csr + beg;
    float2 a0 = {0.f, 0.f}, a1 = {0.f, 0.f}, a2 = {0.f, 0.f}, a3 = {0.f, 0.f};
    int i = slot;
    for (; i + 12 < d; i += 16) {   // 4 edges in flight per slot
        int s0 = __ldg(&cp[i]);
        int s1 = __ldg(&cp[i + 4]);
        int s2 = __ldg(&cp[i + 8]);
        int s3 = __ldg(&cp[i + 12]);
        uint4 v0 = __ldg(&hh[s0 * 8 + q]);
        uint4 v1 = __ldg(&hh[s1 * 8 + q]);
        uint4 v2 = __ldg(&hh[s2 * 8 + q]);
        uint4 v3 = __ldg(&hh[s3 * 8 + q]);
        acc_u4(v0, a0, a1, a2, a3);
        acc_u4(v1, a0, a1, a2, a3);
        acc_u4(v2, a0, a1, a2, a3);
        acc_u4(v3, a0, a1, a2, a3);
    }
    for (; i < d; i += 4) {
        int s = __ldg(&cp[i]);
        uint4 v = __ldg(&hh[s * 8 + q]);
        acc_u4(v, a0, a1, a2, a3);
    }
    // reduce across the 4 slots (lanes differing in bits 3,4)
    a0.x += __shfl_xor_sync(0xffffffffu, a0.x, 8);  a0.x += __shfl_xor_sync(0xffffffffu, a0.x, 16);
    a0.y += __shfl_xor_sync(0xffffffffu, a0.y, 8);  a0.y += __shfl_xor_sync(0xffffffffu, a0.y, 16);
    a1.x += __shfl_xor_sync(0xffffffffu, a1.x, 8);  a1.x += __shfl_xor_sync(0xffffffffu, a1.x, 16);
    a1.y += __shfl_xor_sync(0xffffffffu, a1.y, 8);  a1.y += __shfl_xor_sync(0xffffffffu, a1.y, 16);
    a2.x += __shfl_xor_sync(0xffffffffu, a2.x, 8);  a2.x += __shfl_xor_sync(0xffffffffu, a2.x, 16);
    a2.y += __shfl_xor_sync(0xffffffffu, a2.y, 8);  a2.y += __shfl_xor_sync(0xffffffffu, a2.y, 16);
    a3.x += __shfl_xor_sync(0xffffffffu, a3.x, 8);  a3.x += __shfl_xor_sync(0xffffffffu, a3.x, 16);
    a3.y += __shfl_xor_sync(0xffffffffu, a3.y, 8);  a3.y += __shfl_xor_sync(0xffffffffu, a3.y, 16);
    if (slot == 0) {
        float inv = 1.0f / fmaxf((float)d, 1.0f);
        float4 o0 = make_float4(a0.x * inv, a0.y * inv, a1.x * inv, a1.y * inv);
        float4 o1 = make_float4(a2.x * inv, a2.y * inv, a3.x * inv, a3.y * inv);
        float4* dst = reinterpret_cast<float4*>(aggr + (size_t)node * HID + q * 8);
        dst[0] = o0;
        dst[1] = o1;
    }
}

// =================== proj GEMM: h0 = relu(x @ Wp + bp), scalar FFMA ===================
#define XS_STRIDE 168
#define PROJ_SMEM ((IND * HID + 32 * XS_STRIDE) * 4)

__global__ __launch_bounds__(256) void proj_gemm(
    const float* __restrict__ x, const float* __restrict__ Wp,
    const float* __restrict__ bp, float* __restrict__ out, uint4* __restrict__ hh)
{
    extern __shared__ float sm[];
    float* Ws = sm;                  // [IND][64]
    float* Xs = sm + IND * HID;      // [32][XS_STRIDE]
    const int t = threadIdx.x;
    for (int i = t; i < IND * HID; i += 256) Ws[i] = Wp[i];
    const int cg = t & 15;           // 16 col groups x 4 cols
    const int ng = t >> 4;           // 16 node groups x 2 nodes
    const int c0 = cg * 4;
    float b0 = bp[c0], b1 = bp[c0 + 1], b2 = bp[c0 + 2], b3 = bp[c0 + 3];
    const int ntiles = Nn / 32;      // exact
    for (int tile = blockIdx.x; tile < ntiles; tile += gridDim.x) {
        const int n0 = tile * 32;
        __syncthreads();
        for (int i = t; i < 32 * IND; i += 256) {
            int node = i / IND;
            int c = i - node * IND;
            Xs[node * XS_STRIDE + c] = x[(size_t)(n0 + node) * IND + c];
        }
        __syncthreads();
        float acc[2][4];
        acc[0][0] = b0; acc[0][1] = b1; acc[0][2] = b2; acc[0][3] = b3;
        acc[1][0] = b0; acc[1][1] = b1; acc[1][2] = b2; acc[1][3] = b3;
        const float* xr0 = Xs + (ng * 2 + 0) * XS_STRIDE;
        const float* xr1 = Xs + (ng * 2 + 1) * XS_STRIDE;
        #pragma unroll 4
        for (int k4 = 0; k4 < IND / 4; k4++) {   // 41 iters
            float4 a0 = *reinterpret_cast<const float4*>(xr0 + k4 * 4);
            float4 a1 = *reinterpret_cast<const float4*>(xr1 + k4 * 4);
            #pragma unroll
            for (int kk = 0; kk < 4; kk++) {
                float4 w = *reinterpret_cast<const float4*>(Ws + (k4 * 4 + kk) * HID + c0);
                float av0 = (kk == 0) ? a0.x : (kk == 1) ? a0.y : (kk == 2) ? a0.z : a0.w;
                float av1 = (kk == 0) ? a1.x : (kk == 1) ? a1.y : (kk == 2) ? a1.z : a1.w;
                acc[0][0] = fmaf(av0, w.x, acc[0][0]);
                acc[0][1] = fmaf(av0, w.y, acc[0][1]);
                acc[0][2] = fmaf(av0, w.z, acc[0][2]);
                acc[0][3] = fmaf(av0, w.w, acc[0][3]);
                acc[1][0] = fmaf(av1, w.x, acc[1][0]);
                acc[1][1] = fmaf(av1, w.y, acc[1][1]);
                acc[1][2] = fmaf(av1, w.z, acc[1][2]);
                acc[1][3] = fmaf(av1, w.w, acc[1][3]);
            }
        }
        {   // tail k = 164
            float4 w = *reinterpret_cast<const float4*>(Ws + (IND - 1) * HID + c0);
            float av0 = xr0[IND - 1], av1 = xr1[IND - 1];
            acc[0][0] = fmaf(av0, w.x, acc[0][0]);
            acc[0][1] = fmaf(av0, w.y, acc[0][1]);
            acc[0][2] = fmaf(av0, w.z, acc[0][2]);
            acc[0][3] = fmaf(av0, w.w, acc[0][3]);
            acc[1][0] = fmaf(av1, w.x, acc[1][0]);
            acc[1][1] = fmaf(av1, w.y, acc[1][1]);
            acc[1][2] = fmaf(av1, w.z, acc[1][2]);
            acc[1][3] = fmaf(av1, w.w, acc[1][3]);
        }
        #pragma unroll
        for (int i = 0; i < 2; i++) {
            int n = n0 + ng * 2 + i;
            float4 o;
            o.x = fmaxf(acc[i][0], 0.f);
            o.y = fmaxf(acc[i][1], 0.f);
            o.z = fmaxf(acc[i][2], 0.f);
            o.w = fmaxf(acc[i][3], 0.f);
            *reinterpret_cast<float4*>(out + (size_t)n * HID + c0) = o;
            // fp16 mirror (4 halves = uint2)
            uint2 u;
            u.x = h2u(__floats2half2_rn(o.x, o.y));
            u.y = h2u(__floats2half2_rn(o.z, o.w));
            reinterpret_cast<uint2*>(hh)[(size_t)n * 16 + cg] = u;
        }
    }
}

// ====== SAGE GEMM: out = relu([aggr | h] @ [Wl ; Wr] + bl), scalar FFMA ======
// FINAL=true fuses the classifier: out[n] = relu(row) . Wc + bc
#define AS_STRIDE 132
#define SAGE_SMEM ((128 * HID + 64 * AS_STRIDE) * 4)

template<bool FINAL>
__global__ __launch_bounds__(256) void sage_gemm(
    const float* __restrict__ h, const float* __restrict__ aggr,
    const float* __restrict__ Wl, const float* __restrict__ bl,
    const float* __restrict__ Wr, float* __restrict__ out, uint4* __restrict__ hh,
    const float* __restrict__ Wc, const float* __restrict__ bc)
{
    extern __shared__ float sm[];
    float* Ws = sm;                  // [128][64]: rows 0-63 Wl, 64-127 Wr
    float* As = sm + 128 * HID;      // [64][AS_STRIDE]
    const int t = threadIdx.x;
    for (int i = t; i < HID * HID; i += 256) {
        Ws[i] = Wl[i];
        Ws[HID * HID + i] = Wr[i];
    }
    const int cg = t & 15;           // 16 col groups x 4 cols
    const int ng = t >> 4;           // 16 node groups x 4 nodes
    const int c0 = cg * 4;
    float b0 = bl[c0], b1 = bl[c0 + 1], b2 = bl[c0 + 2], b3 = bl[c0 + 3];
    float4 wc = make_float4(0.f, 0.f, 0.f, 0.f);
    float bc0 = 0.f;
    if (FINAL) {
        wc = *reinterpret_cast<const float4*>(Wc + c0);
        bc0 = bc[0];
    }
    const int ntiles = Nn / 64;      // 3125
    for (int tile = blockIdx.x; tile < ntiles; tile += gridDim.x) {
        const int n0 = tile * 64;
        __syncthreads();
        for (int i = t; i < 64 * 32; i += 256) {
            int node = i >> 5;
            int p = i & 31;
            int n = n0 + node;
            float4 v = (p < 16) ? *reinterpret_cast<const float4*>(aggr + (size_t)n * HID + p * 4)
                                : *reinterpret_cast<const float4*>(h + (size_t)n * HID + (p - 16) * 4);
            *reinterpret_cast<float4*>(As + node * AS_STRIDE + p * 4) = v;
        }
        __syncthreads();
        float acc[4][4];
        #pragma unroll
        for (int i = 0; i < 4; i++) { acc[i][0] = b0; acc[i][1] = b1; acc[i][2] = b2; acc[i][3] = b3; }
        #pragma unroll 2
        for (int k4 = 0; k4 < 32; k4++) {
            float4 a[4];
            #pragma unroll
            for (int i = 0; i < 4; i++)
                a[i] = *reinterpret_cast<const float4*>(As + (ng * 4 + i) * AS_STRIDE + k4 * 4);
            #pragma unroll
            for (int kk = 0; kk < 4; kk++) {
                float4 w = *reinterpret_cast<const float4*>(Ws + (k4 * 4 + kk) * HID + c0);
                #pragma unroll
                for (int i = 0; i < 4; i++) {
                    float av = (kk == 0) ? a[i].x : (kk == 1) ? a[i].y : (kk == 2) ? a[i].z : a[i].w;
                    acc[i][0] = fmaf(av, w.x, acc[i][0]);
                    acc[i][1] = fmaf(av, w.y, acc[i][1]);
                    acc[i][2] = fmaf(av, w.z, acc[i][2]);
                    acc[i][3] = fmaf(av, w.w, acc[i][3]);
                }
            }
        }
        if (FINAL) {
            float part[4];
            #pragma unroll
            for (int i = 0; i < 4; i++) {
                part[i] = fmaxf(acc[i][0], 0.f) * wc.x;
                part[i] = fmaf(fmaxf(acc[i][1], 0.f), wc.y, part[i]);
                part[i] = fmaf(fmaxf(acc[i][2], 0.f), wc.z, part[i]);
                part[i] = fmaf(fmaxf(acc[i][3], 0.f), wc.w, part[i]);
            }
            #pragma unroll
            for (int i = 0; i < 4; i++) {
                #pragma unroll
                for (int o = 1; o < 16; o <<= 1)
                    part[i] += __shfl_xor_sync(0xffffffffu, part[i], o);
            }
            if (cg == 0) {
                #pragma unroll
                for (int i = 0; i < 4; i++)
                    out[n0 + ng * 4 + i] = part[i] + bc0;
            }
        } else {
            #pragma unroll
            for (int i = 0; i < 4; i++) {
                const int n = n0 + ng * 4 + i;
                float4 o;
                o.x = fmaxf(acc[i][0], 0.f);
                o.y = fmaxf(acc[i][1], 0.f);
                o.z = fmaxf(acc[i][2], 0.f);
                o.w = fmaxf(acc[i][3], 0.f);
                *reinterpret_cast<float4*>(out + (size_t)n * HID + c0) = o;
                uint2 u;
                u.x = h2u(__floats2half2_rn(o.x, o.y));
                u.y = h2u(__floats2half2_rn(o.z, o.w));
                reinterpret_cast<uint2*>(hh)[(size_t)n * 16 + cg] = u;
            }
        }
    }
}

extern "C" void kernel_launch(void* const* d_in, const int* in_sizes, int n_in,
                              void* d_out, int out_size)
{
    const float* x   = (const float*)d_in[0];
    const int*   ei  = (const int*)d_in[1];
    const float* Wp  = (const float*)d_in[2];
    const float* bp  = (const float*)d_in[3];
    const float* W1l = (const float*)d_in[4];
    const float* b1l = (const float*)d_in[5];
    const float* W1r = (const float*)d_in[6];
    const float* W2l = (const float*)d_in[7];
    const float* b2l = (const float*)d_in[8];
    const float* W2r = (const float*)d_in[9];
    const float* Wc  = (const float*)d_in[10];
    const float* bc  = (const float*)d_in[11];
    float* out = (float*)d_out;

    const int* src = ei;
    const int* dst = ei + Ee;

    float *h0, *h1, *aggr;
    uint4 *hh0, *hh1;
    int *degi, *off, *cur, *csr, *bsum, *bscan;
    cudaGetSymbolAddress((void**)&h0, g_h0);
    cudaGetSymbolAddress((void**)&h1, g_h1);
    cudaGetSymbolAddress((void**)&aggr, g_aggr);
    cudaGetSymbolAddress((void**)&hh0, g_hh0);
    cudaGetSymbolAddress((void**)&hh1, g_hh1);
    cudaGetSymbolAddress((void**)&degi, g_degi);
    cudaGetSymbolAddress((void**)&off, g_off);
    cudaGetSymbolAddress((void**)&cur, g_cur);
    cudaGetSymbolAddress((void**)&csr, g_csr);
    cudaGetSymbolAddress((void**)&bsum, g_bsum);
    cudaGetSymbolAddress((void**)&bscan, g_bscan);

    static cudaStream_t s2 = nullptr;
    static cudaEvent_t evFork = nullptr, evJoin = nullptr;
    if (!s2) {
        cudaStreamCreateWithFlags(&s2, cudaStreamNonBlocking);
        cudaEventCreateWithFlags(&evFork, cudaEventDisableTiming);
        cudaEventCreateWithFlags(&evJoin, cudaEventDisableTiming);
        cudaFuncSetAttribute(proj_gemm, cudaFuncAttributeMaxDynamicSharedMemorySize, PROJ_SMEM);
        cudaFuncSetAttribute(sage_gemm<false>, cudaFuncAttributeMaxDynamicSharedMemorySize, SAGE_SMEM);
        cudaFuncSetAttribute(sage_gemm<true>, cudaFuncAttributeMaxDynamicSharedMemorySize, SAGE_SMEM);
    }

    // ---- fork: CSR build on side stream, proj on main stream ----
    cudaEventRecord(evFork, 0);
    cudaStreamWaitEvent(s2, evFork, 0);

    cudaMemsetAsync(degi, 0, Nn * sizeof(int), s2);
    deg_kernel<<<(Ee / 4 + 255) / 256, 256, 0, s2>>>(dst, degi);
    scan1<<<NB1K, 256, 0, s2>>>(degi, bsum);
    scan2<<<1, 256, 0, s2>>>(bsum, bscan);
    scan3<<<NB1K, 256, 0, s2>>>(degi, bscan, off, cur);
    place_kernel<<<(Ee / 4 + 255) / 256, 256, 0, s2>>>(src, dst, cur, csr);
    cudaEventRecord(evJoin, s2);

    proj_gemm<<<444, 256, PROJ_SMEM>>>(x, Wp, bp, h0, hh0);

    // ---- join ----
    cudaStreamWaitEvent(0, evJoin, 0);

    // ---- layer 1 ----
    gather_mean_h<<<(Nn * 32 + 255) / 256, 256>>>(csr, off, degi, hh0, aggr);
    sage_gemm<false><<<444, 256, SAGE_SMEM>>>(h0, aggr, W1l, b1l, W1r, h1, hh1, nullptr, nullptr);

    // ---- layer 2 (+ fused classifier) ----
    gather_mean_h<<<(Nn * 32 + 255) / 256, 256>>>(csr, off, degi, hh1, aggr);
    sage_gemm<true><<<444, 256, SAGE_SMEM>>>(h1, aggr, W2l, b2l, W2r, out, nullptr, Wc, bc);
}

// round 10
// speedup vs baseline: 2.0358x; 1.3161x over previous
#include <cuda_runtime.h>
#include <cuda_fp16.h>

#define Nn 200000
#define Ee 3200000
#define IND 165
#define HID 64
#define NB1K 196   // ceil(Nn/1024)

// ---- scratch (no cudaMalloc allowed) ----
__device__ uint4 g_hh0[Nn * 8];   // fp16 h0 rows (64 halves = 8 uint4)
__device__ uint4 g_hh1[Nn * 8];   // fp16 h1 rows
__device__ uint4 g_ag[Nn * 8];    // fp16 aggregated-mean rows
__device__ int   g_degi[Nn];
__device__ int   g_off[Nn];
__device__ int   g_cur[Nn];
__device__ int   g_csr[Ee];
__device__ int   g_bsum[256];
__device__ int   g_bscan[256];

__device__ __forceinline__ unsigned h2u(__half2 h) {
    return *reinterpret_cast<unsigned*>(&h);
}

// =================== degree histogram (int4) ===================
__global__ __launch_bounds__(256) void deg_kernel(const int* __restrict__ dst, int* __restrict__ degi)
{
    int t = blockIdx.x * blockDim.x + threadIdx.x;
    if (t < Ee / 4) {
        int4 d4 = reinterpret_cast<const int4*>(dst)[t];
        atomicAdd(&degi[d4.x], 1);
        atomicAdd(&degi[d4.y], 1);
        atomicAdd(&degi[d4.z], 1);
        atomicAdd(&degi[d4.w], 1);
    }
}

// =================== 2-level exclusive scan ===================
__global__ __launch_bounds__(256) void scan1(const int* __restrict__ degi, int* __restrict__ bsum)
{
    __shared__ int s[256];
    int base = blockIdx.x * 1024 + threadIdx.x * 4;
    int sum = 0;
    #pragma unroll
    for (int i = 0; i < 4; i++) { int n = base + i; if (n < Nn) sum += degi[n]; }
    s[threadIdx.x] = sum; __syncthreads();
    for (int o = 128; o; o >>= 1) {
        if (threadIdx.x < o) s[threadIdx.x] += s[threadIdx.x + o];
        __syncthreads();
    }
    if (threadIdx.x == 0) bsum[blockIdx.x] = s[0];
}

__global__ __launch_bounds__(256) void scan2(const int* __restrict__ bsum, int* __restrict__ bscan)
{
    __shared__ int s[256];
    int v = (threadIdx.x < NB1K) ? bsum[threadIdx.x] : 0;
    s[threadIdx.x] = v; __syncthreads();
    for (int o = 1; o < 256; o <<= 1) {
        int t = (threadIdx.x >= o) ? s[threadIdx.x - o] : 0;
        __syncthreads();
        s[threadIdx.x] += t;
        __syncthreads();
    }
    if (threadIdx.x < NB1K) bscan[threadIdx.x] = s[threadIdx.x] - v;  // exclusive
}

__global__ __launch_bounds__(256) void scan3(const int* __restrict__ degi, const int* __restrict__ bscan,
                                             int* __restrict__ off, int* __restrict__ cur)
{
    __shared__ int s[256];
    int tid = threadIdx.x;
    int base = blockIdx.x * 1024 + tid * 4;
    int d[4]; int sum = 0;
    #pragma unroll
    for (int i = 0; i < 4; i++) { int n = base + i; d[i] = (n < Nn) ? degi[n] : 0; sum += d[i]; }
    s[tid] = sum; __syncthreads();
    for (int o = 1; o < 256; o <<= 1) {
        int t = (tid >= o) ? s[tid - o] : 0;
        __syncthreads();
        s[tid] += t;
        __syncthreads();
    }
    int ex = s[tid] - sum + bscan[blockIdx.x];
    #pragma unroll
    for (int i = 0; i < 4; i++) {
        int n = base + i;
        if (n < Nn) { off[n] = ex; cur[n] = ex; ex += d[i]; }
    }
}

__global__ __launch_bounds__(256) void place_kernel(const int* __restrict__ src, const int* __restrict__ dst,
                                                    int* __restrict__ cur, int* __restrict__ csr)
{
    int t = blockIdx.x * blockDim.x + threadIdx.x;
    if (t < Ee / 4) {
        int4 s4 = reinterpret_cast<const int4*>(src)[t];
        int4 d4 = reinterpret_cast<const int4*>(dst)[t];
        int p;
        p = atomicAdd(&cur[d4.x], 1); csr[p] = s4.x;
        p = atomicAdd(&cur[d4.y], 1); csr[p] = s4.y;
        p = atomicAdd(&cur[d4.z], 1); csr[p] = s4.z;
        p = atomicAdd(&cur[d4.w], 1); csr[p] = s4.w;
    }
}

// ======== gather-mean fp16->fp32->fp16 (warp per node, 4 edge-slots x 8 lanes) ========
__device__ __forceinline__ void acc_u4(const uint4& v, float2& a0, float2& a1, float2& a2, float2& a3)
{
    float2 f;
    f = __half22float2(*reinterpret_cast<const __half2*>(&v.x)); a0.x += f.x; a0.y += f.y;
    f = __half22float2(*reinterpret_cast<const __half2*>(&v.y)); a1.x += f.x; a1.y += f.y;
    f = __half22float2(*reinterpret_cast<const __half2*>(&v.z)); a2.x += f.x; a2.y += f.y;
    f = __half22float2(*reinterpret_cast<const __half2*>(&v.w)); a3.x += f.x; a3.y += f.y;
}

__global__ __launch_bounds__(256) void gather_mean_h(
    const int* __restrict__ csr, const int* __restrict__ off, const int* __restrict__ degi,
    const uint4* __restrict__ hh, uint4* __restrict__ ag)
{
    int node = (int)((blockIdx.x * (unsigned)blockDim.x + threadIdx.x) >> 5);
    if (node >= Nn) return;
    const int lane = threadIdx.x & 31;
    const int slot = lane >> 3;   // 0..3 : edge slot
    const int q = lane & 7;       // 16-byte chunk (cols 8q..8q+7)
    const int beg = off[node];
    const int d = degi[node];
    const int* cp = csr + beg;
    float2 a0 = {0.f, 0.f}, a1 = {0.f, 0.f}, a2 = {0.f, 0.f}, a3 = {0.f, 0.f};
    int i = slot;
    for (; i + 12 < d; i += 16) {   // 4 edges in flight per slot
        int s0 = __ldg(&cp[i]);
        int s1 = __ldg(&cp[i + 4]);
        int s2 = __ldg(&cp[i + 8]);
        int s3 = __ldg(&cp[i + 12]);
        uint4 v0 = __ldg(&hh[s0 * 8 + q]);
        uint4 v1 = __ldg(&hh[s1 * 8 + q]);
        uint4 v2 = __ldg(&hh[s2 * 8 + q]);
        uint4 v3 = __ldg(&hh[s3 * 8 + q]);
        acc_u4(v0, a0, a1, a2, a3);
        acc_u4(v1, a0, a1, a2, a3);
        acc_u4(v2, a0, a1, a2, a3);
        acc_u4(v3, a0, a1, a2, a3);
    }
    for (; i < d; i += 4) {
        int s = __ldg(&cp[i]);
        uint4 v = __ldg(&hh[s * 8 + q]);
        acc_u4(v, a0, a1, a2, a3);
    }
    a0.x += __shfl_xor_sync(0xffffffffu, a0.x, 8);  a0.x += __shfl_xor_sync(0xffffffffu, a0.x, 16);
    a0.y += __shfl_xor_sync(0xffffffffu, a0.y, 8);  a0.y += __shfl_xor_sync(0xffffffffu, a0.y, 16);
    a1.x += __shfl_xor_sync(0xffffffffu, a1.x, 8);  a1.x += __shfl_xor_sync(0xffffffffu, a1.x, 16);
    a1.y += __shfl_xor_sync(0xffffffffu, a1.y, 8);  a1.y += __shfl_xor_sync(0xffffffffu, a1.y, 16);
    a2.x += __shfl_xor_sync(0xffffffffu, a2.x, 8);  a2.x += __shfl_xor_sync(0xffffffffu, a2.x, 16);
    a2.y += __shfl_xor_sync(0xffffffffu, a2.y, 8);  a2.y += __shfl_xor_sync(0xffffffffu, a2.y, 16);
    a3.x += __shfl_xor_sync(0xffffffffu, a3.x, 8);  a3.x += __shfl_xor_sync(0xffffffffu, a3.x, 16);
    a3.y += __shfl_xor_sync(0xffffffffu, a3.y, 8);  a3.y += __shfl_xor_sync(0xffffffffu, a3.y, 16);
    if (slot == 0) {
        float inv = 1.0f / fmaxf((float)d, 1.0f);
        uint4 o;
        o.x = h2u(__floats2half2_rn(a0.x * inv, a0.y * inv));
        o.y = h2u(__floats2half2_rn(a1.x * inv, a1.y * inv));
        o.z = h2u(__floats2half2_rn(a2.x * inv, a2.y * inv));
        o.w = h2u(__floats2half2_rn(a3.x * inv, a3.y * inv));
        ag[(size_t)node * 8 + q] = o;
    }
}

// =================== proj GEMM: hh0 = fp16(relu(x @ Wp + bp)), scalar FFMA ===================
#define XS_STRIDE 168
#define PROJ_SMEM ((IND * HID + 32 * XS_STRIDE) * 4)

__global__ __launch_bounds__(256) void proj_gemm(
    const float* __restrict__ x, const float* __restrict__ Wp,
    const float* __restrict__ bp, uint4* __restrict__ hh)
{
    extern __shared__ float sm[];
    float* Ws = sm;                  // [IND][64]
    float* Xs = sm + IND * HID;      // [32][XS_STRIDE]
    const int t = threadIdx.x;
    for (int i = t; i < IND * HID; i += 256) Ws[i] = Wp[i];
    const int cg = t & 15;
    const int ng = t >> 4;
    const int c0 = cg * 4;
    float b0 = bp[c0], b1 = bp[c0 + 1], b2 = bp[c0 + 2], b3 = bp[c0 + 3];
    const int ntiles = Nn / 32;
    for (int tile = blockIdx.x; tile < ntiles; tile += gridDim.x) {
        const int n0 = tile * 32;
        __syncthreads();
        for (int i = t; i < 32 * IND; i += 256) {
            int node = i / IND;
            int c = i - node * IND;
            Xs[node * XS_STRIDE + c] = x[(size_t)(n0 + node) * IND + c];
        }
        __syncthreads();
        float acc[2][4];
        acc[0][0] = b0; acc[0][1] = b1; acc[0][2] = b2; acc[0][3] = b3;
        acc[1][0] = b0; acc[1][1] = b1; acc[1][2] = b2; acc[1][3] = b3;
        const float* xr0 = Xs + (ng * 2 + 0) * XS_STRIDE;
        const float* xr1 = Xs + (ng * 2 + 1) * XS_STRIDE;
        #pragma unroll 4
        for (int k4 = 0; k4 < IND / 4; k4++) {
            float4 a0 = *reinterpret_cast<const float4*>(xr0 + k4 * 4);
            float4 a1 = *reinterpret_cast<const float4*>(xr1 + k4 * 4);
            #pragma unroll
            for (int kk = 0; kk < 4; kk++) {
                float4 w = *reinterpret_cast<const float4*>(Ws + (k4 * 4 + kk) * HID + c0);
                float av0 = (kk == 0) ? a0.x : (kk == 1) ? a0.y : (kk == 2) ? a0.z : a0.w;
                float av1 = (kk == 0) ? a1.x : (kk == 1) ? a1.y : (kk == 2) ? a1.z : a1.w;
                acc[0][0] = fmaf(av0, w.x, acc[0][0]);
                acc[0][1] = fmaf(av0, w.y, acc[0][1]);
                acc[0][2] = fmaf(av0, w.z, acc[0][2]);
                acc[0][3] = fmaf(av0, w.w, acc[0][3]);
                acc[1][0] = fmaf(av1, w.x, acc[1][0]);
                acc[1][1] = fmaf(av1, w.y, acc[1][1]);
                acc[1][2] = fmaf(av1, w.z, acc[1][2]);
                acc[1][3] = fmaf(av1, w.w, acc[1][3]);
            }
        }
        {   // tail k = 164
            float4 w = *reinterpret_cast<const float4*>(Ws + (IND - 1) * HID + c0);
            float av0 = xr0[IND - 1], av1 = xr1[IND - 1];
            acc[0][0] = fmaf(av0, w.x, acc[0][0]);
            acc[0][1] = fmaf(av0, w.y, acc[0][1]);
            acc[0][2] = fmaf(av0, w.z, acc[0][2]);
            acc[0][3] = fmaf(av0, w.w, acc[0][3]);
            acc[1][0] = fmaf(av1, w.x, acc[1][0]);
            acc[1][1] = fmaf(av1, w.y, acc[1][1]);
            acc[1][2] = fmaf(av1, w.z, acc[1][2]);
            acc[1][3] = fmaf(av1, w.w, acc[1][3]);
        }
        #pragma unroll
        for (int i = 0; i < 2; i++) {
            int n = n0 + ng * 2 + i;
            uint2 u;
            u.x = h2u(__floats2half2_rn(fmaxf(acc[i][0], 0.f), fmaxf(acc[i][1], 0.f)));
            u.y = h2u(__floats2half2_rn(fmaxf(acc[i][2], 0.f), fmaxf(acc[i][3], 0.f)));
            reinterpret_cast<uint2*>(hh)[(size_t)n * 16 + cg] = u;
        }
    }
}

// ====== SAGE via tensor cores: out = relu([ag | hh] @ [Wl ; Wr] + bl) ======
// fp16 inputs, fp32 accumulate (mma.sync.m16n8k16). FINAL fuses classifier.
#define WT_STRIDE 136   // halves; 4g+t bank pattern -> conflict-free
#define AS_STRIDE_H 136 // halves; 272B rows, ldmatrix conflict-free
#define SAGE_SMEM_BYTES (64 * WT_STRIDE * 2 + 64 * AS_STRIDE_H * 2 + 2 * 64 * 4)

template<bool FINAL>
__global__ __launch_bounds__(256) void sage_mma(
    const uint4* __restrict__ hh,      // self rows fp16
    const uint4* __restrict__ ag,      // aggr rows fp16
    const float* __restrict__ Wl, const float* __restrict__ bl,
    const float* __restrict__ Wr,
    unsigned* __restrict__ hh_out,     // non-final: fp16 output rows
    float* __restrict__ out,           // final: [Nn]
    const float* __restrict__ Wc, const float* __restrict__ bc)
{
    extern __shared__ char smraw[];
    __half* Wt = reinterpret_cast<__half*>(smraw);                         // [64 n][WT_STRIDE k]
    __half* As = reinterpret_cast<__half*>(smraw + 64 * WT_STRIDE * 2);    // [64 m][AS_STRIDE_H k]
    float* partial = reinterpret_cast<float*>(smraw + 64 * WT_STRIDE * 2 + 64 * AS_STRIDE_H * 2); // [2][64]
    const int t = threadIdx.x;
    // Wt[n][k]: k<64 -> Wl[k][n], k>=64 -> Wr[k-64][n]
    for (int i = t; i < 64 * 128; i += 256) {
        int n = i >> 7, k = i & 127;
        float v = (k < 64) ? Wl[k * 64 + n] : Wr[(k - 64) * 64 + n];
        Wt[n * WT_STRIDE + k] = __float2half(v);
    }
    const int w = t >> 5, lane = t & 31;
    const int wr = w & 3;        // 16-row block
    const int ch = w >> 2;       // 32-col half
    const int gid = lane >> 2, tig = lane & 3;
    // ldmatrix per-lane address (within warp's 16-row block)
    const unsigned as_base = (unsigned)__cvta_generic_to_shared(As);
    const unsigned lm_base = as_base
        + (unsigned)((wr * 16 + ((lane >> 3) & 1) * 8 + (lane & 7)) * (AS_STRIDE_H * 2))
        + (unsigned)(((lane >> 4) * 8) * 2);
    float bias01[4], bias23[4];
    float wc0[4], wc1[4];
    #pragma unroll
    for (int nt = 0; nt < 4; nt++) {
        int col = ch * 32 + nt * 8 + tig * 2;
        bias01[nt] = bl[col];
        bias23[nt] = bl[col + 1];
        if (FINAL) { wc0[nt] = Wc[col]; wc1[nt] = Wc[col + 1]; }
    }
    float bc0 = FINAL ? bc[0] : 0.f;

    const int ntiles = Nn / 64;  // 3125
    for (int tile = blockIdx.x; tile < ntiles; tile += gridDim.x) {
        const int n0 = tile * 64;
        __syncthreads();
        // fill A tile: row = [ag row (k0-63) | hh row (k64-127)]
        for (int i = t; i < 64 * 16; i += 256) {
            int node = i >> 4, p = i & 15;
            uint4 v = (p < 8) ? ag[(size_t)(n0 + node) * 8 + p]
                              : hh[(size_t)(n0 + node) * 8 + (p - 8)];
            *reinterpret_cast<uint4*>(reinterpret_cast<char*>(As) + node * (AS_STRIDE_H * 2) + p * 16) = v;
        }
        __syncthreads();
        float acc[4][4];
        #pragma unroll
        for (int nt = 0; nt < 4; nt++) {
            acc[nt][0] = bias01[nt]; acc[nt][1] = bias23[nt];
            acc[nt][2] = bias01[nt]; acc[nt][3] = bias23[nt];
        }
        #pragma unroll
        for (int ks = 0; ks < 8; ks++) {
            unsigned a0, a1, a2, a3;
            unsigned addr = lm_base + (unsigned)(ks * 16 * 2);
            asm volatile("ldmatrix.sync.aligned.m8n8.x4.shared.b16 {%0,%1,%2,%3}, [%4];"
                         : "=r"(a0), "=r"(a1), "=r"(a2), "=r"(a3) : "r"(addr));
            #pragma unroll
            for (int nt = 0; nt < 4; nt++) {
                int n = ch * 32 + nt * 8 + gid;
                int k = ks * 16 + tig * 2;
                unsigned b0 = *reinterpret_cast<const unsigned*>(&Wt[n * WT_STRIDE + k]);
                unsigned b1 = *reinterpret_cast<const unsigned*>(&Wt[n * WT_STRIDE + k + 8]);
                asm volatile(
                    "mma.sync.aligned.m16n8k16.row.col.f32.f16.f16.f32 "
                    "{%0,%1,%2,%3}, {%4,%5,%6,%7}, {%8,%9}, {%0,%1,%2,%3};"
                    : "+f"(acc[nt][0]), "+f"(acc[nt][1]), "+f"(acc[nt][2]), "+f"(acc[nt][3])
                    : "r"(a0), "r"(a1), "r"(a2), "r"(a3), "r"(b0), "r"(b1));
            }
        }
        if (FINAL) {
            float s0 = 0.f, s1 = 0.f;
            #pragma unroll
            for (int nt = 0; nt < 4; nt++) {
                s0 = fmaf(fmaxf(acc[nt][0], 0.f), wc0[nt], s0);
                s0 = fmaf(fmaxf(acc[nt][1], 0.f), wc1[nt], s0);
                s1 = fmaf(fmaxf(acc[nt][2], 0.f), wc0[nt], s1);
                s1 = fmaf(fmaxf(acc[nt][3], 0.f), wc1[nt], s1);
            }
            s0 += __shfl_xor_sync(0xffffffffu, s0, 1);
            s0 += __shfl_xor_sync(0xffffffffu, s0, 2);
            s1 += __shfl_xor_sync(0xffffffffu, s1, 1);
            s1 += __shfl_xor_sync(0xffffffffu, s1, 2);
            if (tig == 0) {
                partial[ch * 64 + wr * 16 + gid] = s0;
                partial[ch * 64 + wr * 16 + gid + 8] = s1;
            }
            __syncthreads();
            if (t < 64) out[n0 + t] = partial[t] + partial[64 + t] + bc0;
        } else {
            #pragma unroll
            for (int nt = 0; nt < 4; nt++) {
                int col = ch * 32 + nt * 8 + tig * 2;
                int r0 = n0 + wr * 16 + gid;
                unsigned u0 = h2u(__floats2half2_rn(fmaxf(acc[nt][0], 0.f), fmaxf(acc[nt][1], 0.f)));
                unsigned u1 = h2u(__floats2half2_rn(fmaxf(acc[nt][2], 0.f), fmaxf(acc[nt][3], 0.f)));
                hh_out[(size_t)r0 * 32 + (col >> 1)] = u0;
                hh_out[(size_t)(r0 + 8) * 32 + (col >> 1)] = u1;
            }
        }
    }
}

extern "C" void kernel_launch(void* const* d_in, const int* in_sizes, int n_in,
                              void* d_out, int out_size)
{
    const float* x   = (const float*)d_in[0];
    const int*   ei  = (const int*)d_in[1];
    const float* Wp  = (const float*)d_in[2];
    const float* bp  = (const float*)d_in[3];
    const float* W1l = (const float*)d_in[4];
    const float* b1l = (const float*)d_in[5];
    const float* W1r = (const float*)d_in[6];
    const float* W2l = (const float*)d_in[7];
    const float* b2l = (const float*)d_in[8];
    const float* W2r = (const float*)d_in[9];
    const float* Wc  = (const float*)d_in[10];
    const float* bc  = (const float*)d_in[11];
    float* out = (float*)d_out;

    const int* src = ei;
    const int* dst = ei + Ee;

    uint4 *hh0, *hh1, *ag;
    int *degi, *off, *cur, *csr, *bsum, *bscan;
    cudaGetSymbolAddress((void**)&hh0, g_hh0);
    cudaGetSymbolAddress((void**)&hh1, g_hh1);
    cudaGetSymbolAddress((void**)&ag, g_ag);
    cudaGetSymbolAddress((void**)&degi, g_degi);
    cudaGetSymbolAddress((void**)&off, g_off);
    cudaGetSymbolAddress((void**)&cur, g_cur);
    cudaGetSymbolAddress((void**)&csr, g_csr);
    cudaGetSymbolAddress((void**)&bsum, g_bsum);
    cudaGetSymbolAddress((void**)&bscan, g_bscan);

    static cudaStream_t s2 = nullptr;
    static cudaEvent_t evFork = nullptr, evJoin = nullptr;
    if (!s2) {
        cudaStreamCreateWithFlags(&s2, cudaStreamNonBlocking);
        cudaEventCreateWithFlags(&evFork, cudaEventDisableTiming);
        cudaEventCreateWithFlags(&evJoin, cudaEventDisableTiming);
        cudaFuncSetAttribute(proj_gemm, cudaFuncAttributeMaxDynamicSharedMemorySize, PROJ_SMEM);
    }

    // ---- fork: CSR build on side stream, proj on main stream ----
    cudaEventRecord(evFork, 0);
    cudaStreamWaitEvent(s2, evFork, 0);

    cudaMemsetAsync(degi, 0, Nn * sizeof(int), s2);
    deg_kernel<<<(Ee / 4 + 255) / 256, 256, 0, s2>>>(dst, degi);
    scan1<<<NB1K, 256, 0, s2>>>(degi, bsum);
    scan2<<<1, 256, 0, s2>>>(bsum, bscan);
    scan3<<<NB1K, 256, 0, s2>>>(degi, bscan, off, cur);
    place_kernel<<<(Ee / 4 + 255) / 256, 256, 0, s2>>>(src, dst, cur, csr);
    cudaEventRecord(evJoin, s2);

    proj_gemm<<<444, 256, PROJ_SMEM>>>(x, Wp, bp, hh0);

    // ---- join ----
    cudaStreamWaitEvent(0, evJoin, 0);

    // ---- layer 1 ----
    gather_mean_h<<<(Nn * 32 + 255) / 256, 256>>>(csr, off, degi, hh0, ag);
    sage_mma<false><<<444, 256, SAGE_SMEM_BYTES>>>(hh0, ag, W1l, b1l, W1r,
                                                   (unsigned*)hh1, nullptr, nullptr, nullptr);

    // ---- layer 2 (+ fused classifier) ----
    gather_mean_h<<<(Nn * 32 + 255) / 256, 256>>>(csr, off, degi, hh1, ag);
    sage_mma<true><<<444, 256, SAGE_SMEM_BYTES>>>(hh1, ag, W2l, b2l, W2r,
                                                  nullptr, out, Wc, bc);
}